// round 8
// baseline (speedup 1.0000x reference)
#include <cuda_runtime.h>
#include <cuda_fp16.h>
#include <cstdint>

#define NV 200000
#define KK 27
#define CC 64
#define BM 192
#define NT 384
#define NWARP 12
#define STAGES 2
#define BN_EPS 1e-5f

#define A_BYTES (BM * 128)                         // 24576
#define B_BYTES (CC * 128)                         // 8192
#define STAGE_BYTES (A_BYTES + B_BYTES)            // 32768
#define SMEM_TOTAL (STAGES * STAGE_BYTES)          // 65536 -> 3 CTAs/SM

#define SW(o) ((o) ^ (((o) >> 3) & 0x70))

// ---------------- device scratch ----------------
__device__ alignas(256) __half g_y[(size_t)NV * CC];
__device__ alignas(256) __half g_t16[(size_t)NV * CC];
__device__ alignas(256) __half g_Wh[2][KK * CC * CC];
__device__ float g_sum[2][CC];
__device__ float g_sumsq[2][CC];
__device__ int   g_is64;

// ---------------- helpers ----------------
__device__ __forceinline__ uint32_t smem_u32(const void* p) {
    return (uint32_t)__cvta_generic_to_shared(p);
}
__device__ __forceinline__ void cp16(uint32_t dst, const void* src) {
    asm volatile("cp.async.cg.shared.global [%0], [%1], 16;\n" :: "r"(dst), "l"(src));
}
__device__ __forceinline__ int ld_idx(const void* nbr, bool is64, int gn, int k) {
    size_t pos = (size_t)gn * KK + k;
    return is64 ? (int)((const long long*)nbr)[pos] : ((const int*)nbr)[pos];
}

// ---------------- zero stats + detect index dtype ----------------
__global__ void k_zero(const void* __restrict__ nbr) {
    int t = threadIdx.x;
    if (t < CC) {
        g_sum[0][t] = 0.f; g_sum[1][t] = 0.f;
        g_sumsq[0][t] = 0.f; g_sumsq[1][t] = 0.f;
    }
    if (t == 0) {
        const long long* p = (const long long*)nbr;
        int ok = 1;
        for (int i = 0; i < 64; ++i) {
            long long v = p[i];
            if (v < 0 || v >= NV) { ok = 0; break; }
        }
        g_is64 = ok;
    }
}

// ---------------- weight convert + colstats stage0 ----------------
__global__ void k_prep(const float* __restrict__ x,
                       const float* __restrict__ W1,
                       const float* __restrict__ W2) {
    const int total = KK * CC * CC;
    for (int i = blockIdx.x * blockDim.x + threadIdx.x; i < total;
         i += gridDim.x * blockDim.x) {
        int k  = i >> 12;
        int ci = (i & 4095) >> 6;
        int co = i & 63;
        uint32_t off = (uint32_t)SW(ci * 128 + co * 2) >> 1;
        g_Wh[0][k * 4096 + off] = __float2half_rn(W1[i]);
        g_Wh[1][k * 4096 + off] = __float2half_rn(W2[i]);
    }
    __shared__ float sh[2][4][CC];
    int ch = threadIdx.x & 63;
    int rg = threadIdx.x >> 6;
    float s = 0.f, s2 = 0.f;
    for (int row = blockIdx.x * 4 + rg; row < NV; row += gridDim.x * 4) {
        float v = x[(size_t)row * CC + ch];
        s += v; s2 += v * v;
    }
    sh[0][rg][ch] = s; sh[1][rg][ch] = s2;
    __syncthreads();
    if (rg == 0) {
        s  = sh[0][0][ch] + sh[0][1][ch] + sh[0][2][ch] + sh[0][3][ch];
        s2 = sh[1][0][ch] + sh[1][1][ch] + sh[1][2][ch] + sh[1][3][ch];
        atomicAdd(&g_sum[0][ch], s);
        atomicAdd(&g_sumsq[0][ch], s2);
    }
}

// ---------------- fused finalize + BN + ReLU + fp16 quantize ----------------
__global__ void k_bnrelu(const float* __restrict__ xin,
                         const float* __restrict__ gamma,
                         const float* __restrict__ beta, int stage) {
    __shared__ float s_scale[CC], s_shift[CC];
    if (threadIdx.x < CC) {
        int c = threadIdx.x;
        float mean = g_sum[stage][c] / (float)NV;
        float var  = g_sumsq[stage][c] / (float)NV - mean * mean;
        float s = gamma[c] * rsqrtf(var + BN_EPS);
        s_scale[c] = s;
        s_shift[c] = beta[c] - mean * s;
    }
    __syncthreads();
    const int total = NV * CC / 4;
    for (int i = blockIdx.x * blockDim.x + threadIdx.x; i < total;
         i += gridDim.x * blockDim.x) {
        int cb = (i & 15) << 2;
        float f0, f1, f2, f3;
        if (stage == 0) {
            float4 f = ((const float4*)xin)[i];
            f0 = f.x; f1 = f.y; f2 = f.z; f3 = f.w;
        } else {
            uint2 u = ((const uint2*)g_t16)[i];
            float2 p0 = __half22float2(*(__half2*)&u.x);
            float2 p1 = __half22float2(*(__half2*)&u.y);
            f0 = p0.x; f1 = p0.y; f2 = p1.x; f3 = p1.y;
        }
        float a = fmaxf(fmaf(f0, s_scale[cb + 0], s_shift[cb + 0]), 0.f);
        float b = fmaxf(fmaf(f1, s_scale[cb + 1], s_shift[cb + 1]), 0.f);
        float c = fmaxf(fmaf(f2, s_scale[cb + 2], s_shift[cb + 2]), 0.f);
        float d = fmaxf(fmaf(f3, s_scale[cb + 3], s_shift[cb + 3]), 0.f);
        ((__half2*)g_y)[2 * i]     = __floats2half2_rn(a, b);
        ((__half2*)g_y)[2 * i + 1] = __floats2half2_rn(c, d);
    }
}

// ---------------- gather-GEMM conv: BM=192, 12 warps (6m x 2n, m32n32), occ 3 ----------------
__global__ void __launch_bounds__(NT, 3)
k_conv(const void* __restrict__ nbr, int which,
       const float* __restrict__ residual, float* __restrict__ dout)
{
    extern __shared__ char smem[];
    const uint32_t sb = smem_u32(smem);

    const __half* __restrict__ Wh = g_Wh[which];

    const int tid = threadIdx.x;
    const int warp = tid >> 5, lane = tid & 31;
    const int wm = warp >> 1;          // 0..5 -> 32-row slab
    const int wn = warp & 1;           // 0..1 -> 32-col half
    const int m0 = blockIdx.x * BM;
    const bool is64 = (g_is64 != 0);

    float acc[2][4][4];
    #pragma unroll
    for (int a = 0; a < 2; ++a)
        #pragma unroll
        for (int b = 0; b < 4; ++b)
            #pragma unroll
            for (int c = 0; c < 4; ++c) acc[a][b][c] = 0.f;

    // gather: 2 threads per A row, 64B each
    const int r  = tid >> 1;
    const int hs = tid & 1;
    const int gn = (m0 + r < NV) ? (m0 + r) : 0;

    auto fill = [&](int st, int gi, int k) {
        const __half* srcA = g_y + (size_t)gi * CC + hs * 32;
        uint32_t abase = sb + st * STAGE_BYTES;
        #pragma unroll
        for (int j = 0; j < 4; ++j) {
            uint32_t boff = (uint32_t)(r * 128 + (hs * 4 + j) * 16);
            cp16(abase + SW(boff), srcA + j * 8);
        }
        const __half* srcB = Wh + k * 4096;
        uint32_t bbase = abase + A_BYTES;
        cp16(bbase + tid * 16, srcB + tid * 8);
        if (tid < 128)
            cp16(bbase + (tid + NT) * 16, srcB + (tid + NT) * 8);
    };

    {
        int i0 = ld_idx(nbr, is64, gn, 0);
        int i1 = ld_idx(nbr, is64, gn, 1);
        fill(0, i0, 0);
        asm volatile("cp.async.commit_group;\n");
        fill(1, i1, 1);
        asm volatile("cp.async.commit_group;\n");
    }
    int gi_next = ld_idx(nbr, is64, gn, 2);

    for (int k = 0; k < KK; ++k) {
        const int st = k & 1;
        if (k + 1 < KK)
            asm volatile("cp.async.wait_group 1;\n");
        else
            asm volatile("cp.async.wait_group 0;\n");
        __syncthreads();

        const uint32_t abase = sb + st * STAGE_BYTES;
        const uint32_t bbase = abase + A_BYTES;

        #pragma unroll
        for (int ks = 0; ks < 4; ++ks) {
            const int k0 = ks * 16;
            uint32_t a0[4], a1[4];
            {
                int row = wm * 32 + (lane & 15);
                int col = k0 + (lane >> 4) * 8;
                uint32_t ad = abase + SW((uint32_t)(row * 128 + col * 2));
                asm volatile("ldmatrix.sync.aligned.m8n8.x4.shared.b16 {%0,%1,%2,%3}, [%4];"
                             : "=r"(a0[0]), "=r"(a0[1]), "=r"(a0[2]), "=r"(a0[3]) : "r"(ad));
                ad = abase + SW((uint32_t)((row + 16) * 128 + col * 2));
                asm volatile("ldmatrix.sync.aligned.m8n8.x4.shared.b16 {%0,%1,%2,%3}, [%4];"
                             : "=r"(a1[0]), "=r"(a1[1]), "=r"(a1[2]), "=r"(a1[3]) : "r"(ad));
            }
            uint32_t b0[4], b1[4];
            {
                int krow = k0 + ((lane >> 3) & 1) * 8 + (lane & 7);
                int coll = wn * 32 + (lane >> 4) * 8;
                uint32_t ad = bbase + SW((uint32_t)(krow * 128 + coll * 2));
                asm volatile("ldmatrix.sync.aligned.m8n8.x4.trans.shared.b16 {%0,%1,%2,%3}, [%4];"
                             : "=r"(b0[0]), "=r"(b0[1]), "=r"(b0[2]), "=r"(b0[3]) : "r"(ad));
                ad = bbase + SW((uint32_t)(krow * 128 + (coll + 16) * 2));
                asm volatile("ldmatrix.sync.aligned.m8n8.x4.trans.shared.b16 {%0,%1,%2,%3}, [%4];"
                             : "=r"(b1[0]), "=r"(b1[1]), "=r"(b1[2]), "=r"(b1[3]) : "r"(ad));
            }
            #pragma unroll
            for (int mt = 0; mt < 2; ++mt) {
                const uint32_t* A = mt ? a1 : a0;
                #pragma unroll
                for (int nt = 0; nt < 4; ++nt) {
                    const uint32_t* B = (nt < 2) ? b0 : b1;
                    uint32_t bb0 = B[(nt & 1) * 2], bb1 = B[(nt & 1) * 2 + 1];
                    float* C = acc[mt][nt];
                    asm volatile(
                        "mma.sync.aligned.m16n8k16.row.col.f32.f16.f16.f32 "
                        "{%0,%1,%2,%3}, {%4,%5,%6,%7}, {%8,%9}, {%0,%1,%2,%3};"
                        : "+f"(C[0]), "+f"(C[1]), "+f"(C[2]), "+f"(C[3])
                        : "r"(A[0]), "r"(A[1]), "r"(A[2]), "r"(A[3]),
                          "r"(bb0), "r"(bb1));
                }
            }
        }

        if (k + 2 < KK) {
            __syncthreads();
            fill(st, gi_next, k + 2);
            asm volatile("cp.async.commit_group;\n");
            gi_next = ld_idx(nbr, is64, gn, (k + 3 < KK) ? (k + 3) : (KK - 1));
        }
    }

    // ---- epilogue ----
    if (which == 0) {
        // conv1: write fp16 + fused per-channel stats (stage 1)
        float ls[8], lq[8];
        #pragma unroll
        for (int j = 0; j < 8; ++j) { ls[j] = 0.f; lq[j] = 0.f; }

        #pragma unroll
        for (int mt = 0; mt < 2; ++mt) {
            int rbase = m0 + wm * 32 + mt * 16 + (lane >> 2);
            bool v0 = rbase < NV, v1 = rbase + 8 < NV;
            #pragma unroll
            for (int nt = 0; nt < 4; ++nt) {
                int col = wn * 32 + nt * 8 + (lane & 3) * 2;
                float* C = acc[mt][nt];
                if (v0) {
                    size_t o = (size_t)rbase * CC + col;
                    *(__half2*)(g_t16 + o) = __floats2half2_rn(C[0], C[1]);
                    ls[nt * 2]     += C[0]; lq[nt * 2]     += C[0] * C[0];
                    ls[nt * 2 + 1] += C[1]; lq[nt * 2 + 1] += C[1] * C[1];
                }
                if (v1) {
                    size_t o = (size_t)(rbase + 8) * CC + col;
                    *(__half2*)(g_t16 + o) = __floats2half2_rn(C[2], C[3]);
                    ls[nt * 2]     += C[2]; lq[nt * 2]     += C[2] * C[2];
                    ls[nt * 2 + 1] += C[3]; lq[nt * 2 + 1] += C[3] * C[3];
                }
            }
        }
        // shuffle-reduce across the 8 row-threads (lane bits 2..4)
        #pragma unroll
        for (int m = 4; m <= 16; m <<= 1) {
            #pragma unroll
            for (int j = 0; j < 8; ++j) {
                ls[j] += __shfl_xor_sync(0xffffffffu, ls[j], m);
                lq[j] += __shfl_xor_sync(0xffffffffu, lq[j], m);
            }
        }
        // per-warp partials -> smem (no atomics), then cross-warp sum -> global RED
        float* red = (float*)smem;   // [2][NWARP][32] = 3 KB
        __syncthreads();
        if ((lane >> 2) == 0) {
            #pragma unroll
            for (int j = 0; j < 8; ++j) {
                int cl = (j >> 1) * 8 + (lane & 3) * 2 + (j & 1);
                red[warp * 32 + cl]                = ls[j];
                red[NWARP * 32 + warp * 32 + cl]   = lq[j];
            }
        }
        __syncthreads();
        if (tid < 128) {
            int part = tid >> 6, c = tid & 63;
            int cwn = c >> 5, cl = c & 31;
            const float* base = red + part * NWARP * 32;
            float v = 0.f;
            #pragma unroll
            for (int i = 0; i < 6; ++i) v += base[(2 * i + cwn) * 32 + cl];
            atomicAdd(part ? &g_sumsq[1][c] : &g_sum[1][c], v);
        }
    } else {
        // conv2: fp32 out + residual
        #pragma unroll
        for (int mt = 0; mt < 2; ++mt) {
            int rbase = m0 + wm * 32 + mt * 16 + (lane >> 2);
            #pragma unroll
            for (int nt = 0; nt < 4; ++nt) {
                int col = wn * 32 + nt * 8 + (lane & 3) * 2;
                float* C = acc[mt][nt];
                if (rbase < NV) {
                    size_t o = (size_t)rbase * CC + col;
                    dout[o]     = C[0] + residual[o];
                    dout[o + 1] = C[1] + residual[o + 1];
                }
                if (rbase + 8 < NV) {
                    size_t o = (size_t)(rbase + 8) * CC + col;
                    dout[o]     = C[2] + residual[o];
                    dout[o + 1] = C[3] + residual[o + 1];
                }
            }
        }
    }
}

// ---------------- launch ----------------
extern "C" void kernel_launch(void* const* d_in, const int* in_sizes, int n_in,
                              void* d_out, int out_size) {
    const float* x      = (const float*)d_in[0];
    const void*  nbr    = d_in[1];
    const float* W1     = (const float*)d_in[2];
    const float* gamma1 = (const float*)d_in[3];
    const float* beta1  = (const float*)d_in[4];
    const float* W2     = (const float*)d_in[5];
    const float* gamma2 = (const float*)d_in[6];
    const float* beta2  = (const float*)d_in[7];
    float* out = (float*)d_out;

    const int conv_grid = (NV + BM - 1) / BM;   // 1042

    static int attr_set = 0;
    if (!attr_set) {
        cudaFuncSetAttribute(k_conv, cudaFuncAttributeMaxDynamicSharedMemorySize,
                             SMEM_TOTAL);
        attr_set = 1;
    }

    k_zero<<<1, 64>>>(nbr);                                         // 1
    k_prep<<<512, 256>>>(x, W1, W2);                                // 2
    k_bnrelu<<<2048, 256>>>(x, gamma1, beta1, 0);                   // 3
    k_conv<<<conv_grid, NT, SMEM_TOTAL>>>(nbr, 0, nullptr, nullptr);// 4 <- ncu
    k_bnrelu<<<2048, 256>>>(nullptr, gamma2, beta2, 1);             // 5
    k_conv<<<conv_grid, NT, SMEM_TOTAL>>>(nbr, 1, x, out);          // 6
}

// round 9
// speedup vs baseline: 1.2226x; 1.2226x over previous
#include <cuda_runtime.h>
#include <cuda_fp16.h>
#include <cstdint>

#define NV 200000
#define KK 27
#define CC 64
#define BM 128
#define NT 256
#define NWARP 8
#define STAGES 2
#define BN_EPS 1e-5f

#define A_BYTES (BM * 128)
#define B_BYTES (CC * 128)
#define STAGE_BYTES (A_BYTES + B_BYTES)           // 24576
#define SMEM_TOTAL (STAGES * STAGE_BYTES)         // 49152 -> 4 CTAs/SM

#define SW(o) ((o) ^ (((o) >> 3) & 0x70))

// ---------------- device scratch ----------------
__device__ alignas(256) __half g_y[(size_t)NV * CC];
__device__ alignas(256) __half g_t16[(size_t)NV * CC];
__device__ alignas(256) __half g_Wh[2][KK * CC * CC];
__device__ float g_sum[2][CC];
__device__ float g_sumsq[2][CC];
__device__ int   g_is64;

// ---------------- helpers ----------------
__device__ __forceinline__ uint32_t smem_u32(const void* p) {
    return (uint32_t)__cvta_generic_to_shared(p);
}
__device__ __forceinline__ void cp16(uint32_t dst, const void* src) {
    asm volatile("cp.async.cg.shared.global [%0], [%1], 16;\n" :: "r"(dst), "l"(src));
}
__device__ __forceinline__ int ld_idx(const void* nbr, bool is64, int gn, int k) {
    size_t pos = (size_t)gn * KK + k;
    return is64 ? (int)((const long long*)nbr)[pos] : ((const int*)nbr)[pos];
}

// ---------------- zero stats + detect index dtype ----------------
__global__ void k_zero(const void* __restrict__ nbr) {
    int t = threadIdx.x;
    if (t < CC) {
        g_sum[0][t] = 0.f; g_sum[1][t] = 0.f;
        g_sumsq[0][t] = 0.f; g_sumsq[1][t] = 0.f;
    }
    if (t == 0) {
        const long long* p = (const long long*)nbr;
        int ok = 1;
        for (int i = 0; i < 64; ++i) {
            long long v = p[i];
            if (v < 0 || v >= NV) { ok = 0; break; }
        }
        g_is64 = ok;
    }
}

// ---------------- weight convert + colstats stage0 ----------------
__global__ void k_prep(const float* __restrict__ x,
                       const float* __restrict__ W1,
                       const float* __restrict__ W2) {
    const int total = KK * CC * CC;
    for (int i = blockIdx.x * blockDim.x + threadIdx.x; i < total;
         i += gridDim.x * blockDim.x) {
        int k  = i >> 12;
        int ci = (i & 4095) >> 6;
        int co = i & 63;
        uint32_t off = (uint32_t)SW(ci * 128 + co * 2) >> 1;
        g_Wh[0][k * 4096 + off] = __float2half_rn(W1[i]);
        g_Wh[1][k * 4096 + off] = __float2half_rn(W2[i]);
    }
    __shared__ float sh[2][4][CC];
    int ch = threadIdx.x & 63;
    int rg = threadIdx.x >> 6;
    float s = 0.f, s2 = 0.f;
    for (int row = blockIdx.x * 4 + rg; row < NV; row += gridDim.x * 4) {
        float v = x[(size_t)row * CC + ch];
        s += v; s2 += v * v;
    }
    sh[0][rg][ch] = s; sh[1][rg][ch] = s2;
    __syncthreads();
    if (rg == 0) {
        s  = sh[0][0][ch] + sh[0][1][ch] + sh[0][2][ch] + sh[0][3][ch];
        s2 = sh[1][0][ch] + sh[1][1][ch] + sh[1][2][ch] + sh[1][3][ch];
        atomicAdd(&g_sum[0][ch], s);
        atomicAdd(&g_sumsq[0][ch], s2);
    }
}

// ---------------- fused finalize + BN + ReLU + fp16 quantize ----------------
__global__ void k_bnrelu(const float* __restrict__ xin,
                         const float* __restrict__ gamma,
                         const float* __restrict__ beta, int stage) {
    __shared__ float s_scale[CC], s_shift[CC];
    if (threadIdx.x < CC) {
        int c = threadIdx.x;
        float mean = g_sum[stage][c] / (float)NV;
        float var  = g_sumsq[stage][c] / (float)NV - mean * mean;
        float s = gamma[c] * rsqrtf(var + BN_EPS);
        s_scale[c] = s;
        s_shift[c] = beta[c] - mean * s;
    }
    __syncthreads();
    const int total = NV * CC / 4;
    for (int i = blockIdx.x * blockDim.x + threadIdx.x; i < total;
         i += gridDim.x * blockDim.x) {
        int cb = (i & 15) << 2;
        float f0, f1, f2, f3;
        if (stage == 0) {
            float4 f = ((const float4*)xin)[i];
            f0 = f.x; f1 = f.y; f2 = f.z; f3 = f.w;
        } else {
            uint2 u = ((const uint2*)g_t16)[i];
            float2 p0 = __half22float2(*(__half2*)&u.x);
            float2 p1 = __half22float2(*(__half2*)&u.y);
            f0 = p0.x; f1 = p0.y; f2 = p1.x; f3 = p1.y;
        }
        float a = fmaxf(fmaf(f0, s_scale[cb + 0], s_shift[cb + 0]), 0.f);
        float b = fmaxf(fmaf(f1, s_scale[cb + 1], s_shift[cb + 1]), 0.f);
        float c = fmaxf(fmaf(f2, s_scale[cb + 2], s_shift[cb + 2]), 0.f);
        float d = fmaxf(fmaf(f3, s_scale[cb + 3], s_shift[cb + 3]), 0.f);
        ((__half2*)g_y)[2 * i]     = __floats2half2_rn(a, b);
        ((__half2*)g_y)[2 * i + 1] = __floats2half2_rn(c, d);
    }
}

// ---------------- gather-GEMM conv: BM=128, 8 warps (4m x 2n, m32n32), occ 4 ----------------
__global__ void __launch_bounds__(NT, 4)
k_conv(const void* __restrict__ nbr, int which,
       const float* __restrict__ residual, float* __restrict__ dout)
{
    extern __shared__ char smem[];
    const uint32_t sb = smem_u32(smem);

    const __half* __restrict__ Wh = g_Wh[which];

    const int tid = threadIdx.x;
    const int warp = tid >> 5, lane = tid & 31;
    const int wm = warp >> 1;          // 0..3 -> 32-row slab
    const int wn = warp & 1;           // 0..1 -> 32-col half
    const int m0 = blockIdx.x * BM;
    const bool is64 = (g_is64 != 0);

    float acc[2][4][4];
    #pragma unroll
    for (int a = 0; a < 2; ++a)
        #pragma unroll
        for (int b = 0; b < 4; ++b)
            #pragma unroll
            for (int c = 0; c < 4; ++c) acc[a][b][c] = 0.f;

    const int r  = tid >> 1;
    const int hs = tid & 1;
    const int gn = (m0 + r < NV) ? (m0 + r) : 0;

    auto fill = [&](int st, int gi, int k) {
        const __half* srcA = g_y + (size_t)gi * CC + hs * 32;
        uint32_t abase = sb + st * STAGE_BYTES;
        #pragma unroll
        for (int j = 0; j < 4; ++j) {
            uint32_t boff = (uint32_t)(r * 128 + (hs * 4 + j) * 16);
            cp16(abase + SW(boff), srcA + j * 8);
        }
        const __half* srcB = Wh + k * 4096;
        uint32_t bbase = abase + A_BYTES;
        cp16(bbase + tid * 16,        srcB + tid * 8);
        cp16(bbase + (tid + NT) * 16, srcB + (tid + NT) * 8);
    };

    {
        int i0 = ld_idx(nbr, is64, gn, 0);
        int i1 = ld_idx(nbr, is64, gn, 1);
        fill(0, i0, 0);
        asm volatile("cp.async.commit_group;\n");
        fill(1, i1, 1);
        asm volatile("cp.async.commit_group;\n");
    }
    int gi_next = ld_idx(nbr, is64, gn, 2);

    for (int k = 0; k < KK; ++k) {
        const int st = k & 1;
        if (k + 1 < KK)
            asm volatile("cp.async.wait_group 1;\n");
        else
            asm volatile("cp.async.wait_group 0;\n");
        __syncthreads();

        const uint32_t abase = sb + st * STAGE_BYTES;
        const uint32_t bbase = abase + A_BYTES;

        #pragma unroll
        for (int ks = 0; ks < 4; ++ks) {
            const int k0 = ks * 16;
            uint32_t a0[4], a1[4];
            {
                int row = wm * 32 + (lane & 15);
                int col = k0 + (lane >> 4) * 8;
                uint32_t ad = abase + SW((uint32_t)(row * 128 + col * 2));
                asm volatile("ldmatrix.sync.aligned.m8n8.x4.shared.b16 {%0,%1,%2,%3}, [%4];"
                             : "=r"(a0[0]), "=r"(a0[1]), "=r"(a0[2]), "=r"(a0[3]) : "r"(ad));
                ad = abase + SW((uint32_t)((row + 16) * 128 + col * 2));
                asm volatile("ldmatrix.sync.aligned.m8n8.x4.shared.b16 {%0,%1,%2,%3}, [%4];"
                             : "=r"(a1[0]), "=r"(a1[1]), "=r"(a1[2]), "=r"(a1[3]) : "r"(ad));
            }
            uint32_t b0[4], b1[4];
            {
                int krow = k0 + ((lane >> 3) & 1) * 8 + (lane & 7);
                int coll = wn * 32 + (lane >> 4) * 8;
                uint32_t ad = bbase + SW((uint32_t)(krow * 128 + coll * 2));
                asm volatile("ldmatrix.sync.aligned.m8n8.x4.trans.shared.b16 {%0,%1,%2,%3}, [%4];"
                             : "=r"(b0[0]), "=r"(b0[1]), "=r"(b0[2]), "=r"(b0[3]) : "r"(ad));
                ad = bbase + SW((uint32_t)(krow * 128 + (coll + 16) * 2));
                asm volatile("ldmatrix.sync.aligned.m8n8.x4.trans.shared.b16 {%0,%1,%2,%3}, [%4];"
                             : "=r"(b1[0]), "=r"(b1[1]), "=r"(b1[2]), "=r"(b1[3]) : "r"(ad));
            }
            #pragma unroll
            for (int mt = 0; mt < 2; ++mt) {
                const uint32_t* A = mt ? a1 : a0;
                #pragma unroll
                for (int nt = 0; nt < 4; ++nt) {
                    const uint32_t* B = (nt < 2) ? b0 : b1;
                    uint32_t bb0 = B[(nt & 1) * 2], bb1 = B[(nt & 1) * 2 + 1];
                    float* C = acc[mt][nt];
                    asm volatile(
                        "mma.sync.aligned.m16n8k16.row.col.f32.f16.f16.f32 "
                        "{%0,%1,%2,%3}, {%4,%5,%6,%7}, {%8,%9}, {%0,%1,%2,%3};"
                        : "+f"(C[0]), "+f"(C[1]), "+f"(C[2]), "+f"(C[3])
                        : "r"(A[0]), "r"(A[1]), "r"(A[2]), "r"(A[3]),
                          "r"(bb0), "r"(bb1));
                }
            }
        }

        if (k + 2 < KK) {
            __syncthreads();
            fill(st, gi_next, k + 2);
            asm volatile("cp.async.commit_group;\n");
            gi_next = ld_idx(nbr, is64, gn, (k + 3 < KK) ? (k + 3) : (KK - 1));
        }
    }

    // ---- epilogue ----
    if (which == 0) {
        // conv1: write fp16 + fused per-channel stats (shuffle reduce, no atomics)
        float ls[8], lq[8];
        #pragma unroll
        for (int j = 0; j < 8; ++j) { ls[j] = 0.f; lq[j] = 0.f; }

        #pragma unroll
        for (int mt = 0; mt < 2; ++mt) {
            int rbase = m0 + wm * 32 + mt * 16 + (lane >> 2);
            bool v0 = rbase < NV, v1 = rbase + 8 < NV;
            #pragma unroll
            for (int nt = 0; nt < 4; ++nt) {
                int col = wn * 32 + nt * 8 + (lane & 3) * 2;
                float* C = acc[mt][nt];
                if (v0) {
                    size_t o = (size_t)rbase * CC + col;
                    *(__half2*)(g_t16 + o) = __floats2half2_rn(C[0], C[1]);
                    ls[nt * 2]     += C[0]; lq[nt * 2]     += C[0] * C[0];
                    ls[nt * 2 + 1] += C[1]; lq[nt * 2 + 1] += C[1] * C[1];
                }
                if (v1) {
                    size_t o = (size_t)(rbase + 8) * CC + col;
                    *(__half2*)(g_t16 + o) = __floats2half2_rn(C[2], C[3]);
                    ls[nt * 2]     += C[2]; lq[nt * 2]     += C[2] * C[2];
                    ls[nt * 2 + 1] += C[3]; lq[nt * 2 + 1] += C[3] * C[3];
                }
            }
        }
        #pragma unroll
        for (int m = 4; m <= 16; m <<= 1) {
            #pragma unroll
            for (int j = 0; j < 8; ++j) {
                ls[j] += __shfl_xor_sync(0xffffffffu, ls[j], m);
                lq[j] += __shfl_xor_sync(0xffffffffu, lq[j], m);
            }
        }
        float* red = (float*)smem;   // [2][NWARP][32] = 2 KB
        __syncthreads();
        if ((lane >> 2) == 0) {
            #pragma unroll
            for (int j = 0; j < 8; ++j) {
                int cl = (j >> 1) * 8 + (lane & 3) * 2 + (j & 1);
                red[warp * 32 + cl]              = ls[j];
                red[NWARP * 32 + warp * 32 + cl] = lq[j];
            }
        }
        __syncthreads();
        if (tid < 128) {
            int part = tid >> 6, c = tid & 63;
            int cwn = c >> 5, cl = c & 31;
            const float* base = red + part * NWARP * 32;
            float v = 0.f;
            #pragma unroll
            for (int i = 0; i < 4; ++i) v += base[(2 * i + cwn) * 32 + cl];
            atomicAdd(part ? &g_sumsq[1][c] : &g_sum[1][c], v);
        }
    } else {
        // conv2: fp32 out + residual
        #pragma unroll
        for (int mt = 0; mt < 2; ++mt) {
            int rbase = m0 + wm * 32 + mt * 16 + (lane >> 2);
            #pragma unroll
            for (int nt = 0; nt < 4; ++nt) {
                int col = wn * 32 + nt * 8 + (lane & 3) * 2;
                float* C = acc[mt][nt];
                if (rbase < NV) {
                    size_t o = (size_t)rbase * CC + col;
                    dout[o]     = C[0] + residual[o];
                    dout[o + 1] = C[1] + residual[o + 1];
                }
                if (rbase + 8 < NV) {
                    size_t o = (size_t)(rbase + 8) * CC + col;
                    dout[o]     = C[2] + residual[o];
                    dout[o + 1] = C[3] + residual[o + 1];
                }
            }
        }
    }
}

// ---------------- launch ----------------
extern "C" void kernel_launch(void* const* d_in, const int* in_sizes, int n_in,
                              void* d_out, int out_size) {
    const float* x      = (const float*)d_in[0];
    const void*  nbr    = d_in[1];
    const float* W1     = (const float*)d_in[2];
    const float* gamma1 = (const float*)d_in[3];
    const float* beta1  = (const float*)d_in[4];
    const float* W2     = (const float*)d_in[5];
    const float* gamma2 = (const float*)d_in[6];
    const float* beta2  = (const float*)d_in[7];
    float* out = (float*)d_out;

    const int conv_grid = (NV + BM - 1) / BM;   // 1563

    static int attr_set = 0;
    if (!attr_set) {
        cudaFuncSetAttribute(k_conv, cudaFuncAttributeMaxDynamicSharedMemorySize,
                             SMEM_TOTAL);
        attr_set = 1;
    }

    k_zero<<<1, 64>>>(nbr);                                         // 1
    k_prep<<<512, 256>>>(x, W1, W2);                                // 2
    k_bnrelu<<<2048, 256>>>(x, gamma1, beta1, 0);                   // 3
    k_conv<<<conv_grid, NT, SMEM_TOTAL>>>(nbr, 0, nullptr, nullptr);// 4 <- ncu
    k_bnrelu<<<2048, 256>>>(nullptr, gamma2, beta2, 1);             // 5
    k_conv<<<conv_grid, NT, SMEM_TOTAL>>>(nbr, 1, x, out);          // 6
}

// round 10
// speedup vs baseline: 1.2260x; 1.0028x over previous
#include <cuda_runtime.h>
#include <cuda_fp16.h>
#include <cstdint>

#define NV 200000
#define KK 27
#define CC 64
#define BM 128
#define NT 256
#define NWARP 8
#define STAGES 2
#define BN_EPS 1e-5f

#define A_BYTES (BM * 128)
#define B_BYTES (CC * 128)
#define STAGE_BYTES (A_BYTES + B_BYTES)           // 24576
#define SMEM_TOTAL (STAGES * STAGE_BYTES)         // 49152 -> 4 CTAs/SM

#define SW(o) ((o) ^ (((o) >> 3) & 0x70))

// ---------------- device scratch ----------------
__device__ alignas(256) __half g_y[(size_t)NV * CC];
__device__ alignas(256) __half g_t16[(size_t)NV * CC];
__device__ alignas(256) __half g_Wh[2][KK * CC * CC];
__device__ float g_sum[2][CC];
__device__ float g_sumsq[2][CC];
__device__ int   g_is64;

// ---------------- helpers ----------------
__device__ __forceinline__ uint32_t smem_u32(const void* p) {
    return (uint32_t)__cvta_generic_to_shared(p);
}
__device__ __forceinline__ void cp16(uint32_t dst, const void* src) {
    asm volatile("cp.async.cg.shared.global [%0], [%1], 16;\n" :: "r"(dst), "l"(src));
}
__device__ __forceinline__ int ld_idx(const void* nbr, bool is64, int gn, int k) {
    size_t pos = (size_t)gn * KK + k;
    return is64 ? (int)((const long long*)nbr)[pos] : ((const int*)nbr)[pos];
}

// ---------------- zero stats + detect index dtype ----------------
__global__ void k_zero(const void* __restrict__ nbr) {
    int t = threadIdx.x;
    if (t < CC) {
        g_sum[0][t] = 0.f; g_sum[1][t] = 0.f;
        g_sumsq[0][t] = 0.f; g_sumsq[1][t] = 0.f;
    }
    if (t == 0) {
        const long long* p = (const long long*)nbr;
        int ok = 1;
        for (int i = 0; i < 64; ++i) {
            long long v = p[i];
            if (v < 0 || v >= NV) { ok = 0; break; }
        }
        g_is64 = ok;
    }
}

// ---------------- weight convert + colstats stage0 ----------------
__global__ void k_prep(const float* __restrict__ x,
                       const float* __restrict__ W1,
                       const float* __restrict__ W2) {
    const int total = KK * CC * CC;
    for (int i = blockIdx.x * blockDim.x + threadIdx.x; i < total;
         i += gridDim.x * blockDim.x) {
        int k  = i >> 12;
        int ci = (i & 4095) >> 6;
        int co = i & 63;
        uint32_t off = (uint32_t)SW(ci * 128 + co * 2) >> 1;
        g_Wh[0][k * 4096 + off] = __float2half_rn(W1[i]);
        g_Wh[1][k * 4096 + off] = __float2half_rn(W2[i]);
    }
    __shared__ float sh[2][4][CC];
    int ch = threadIdx.x & 63;
    int rg = threadIdx.x >> 6;
    float s = 0.f, s2 = 0.f;
    for (int row = blockIdx.x * 4 + rg; row < NV; row += gridDim.x * 4) {
        float v = x[(size_t)row * CC + ch];
        s += v; s2 += v * v;
    }
    sh[0][rg][ch] = s; sh[1][rg][ch] = s2;
    __syncthreads();
    if (rg == 0) {
        s  = sh[0][0][ch] + sh[0][1][ch] + sh[0][2][ch] + sh[0][3][ch];
        s2 = sh[1][0][ch] + sh[1][1][ch] + sh[1][2][ch] + sh[1][3][ch];
        atomicAdd(&g_sum[0][ch], s);
        atomicAdd(&g_sumsq[0][ch], s2);
    }
}

// ---------------- fused finalize + BN + ReLU + fp16 quantize (8 elems/thread) ----------------
__global__ void k_bnrelu(const float* __restrict__ xin,
                         const float* __restrict__ gamma,
                         const float* __restrict__ beta, int stage) {
    __shared__ float s_scale[CC], s_shift[CC];
    if (threadIdx.x < CC) {
        int c = threadIdx.x;
        float mean = g_sum[stage][c] / (float)NV;
        float var  = g_sumsq[stage][c] / (float)NV - mean * mean;
        float s = gamma[c] * rsqrtf(var + BN_EPS);
        s_scale[c] = s;
        s_shift[c] = beta[c] - mean * s;
    }
    __syncthreads();
    const int total = NV * CC / 8;     // uint4-granular (8 halves out)
    for (int i = blockIdx.x * blockDim.x + threadIdx.x; i < total;
         i += gridDim.x * blockDim.x) {
        int cb = (i & 7) << 3;
        float f[8];
        if (stage == 0) {
            float4 u0 = ((const float4*)xin)[2 * i];
            float4 u1 = ((const float4*)xin)[2 * i + 1];
            f[0] = u0.x; f[1] = u0.y; f[2] = u0.z; f[3] = u0.w;
            f[4] = u1.x; f[5] = u1.y; f[6] = u1.z; f[7] = u1.w;
        } else {
            uint4 u = ((const uint4*)g_t16)[i];
            float2 p0 = __half22float2(*(__half2*)&u.x);
            float2 p1 = __half22float2(*(__half2*)&u.y);
            float2 p2 = __half22float2(*(__half2*)&u.z);
            float2 p3 = __half22float2(*(__half2*)&u.w);
            f[0] = p0.x; f[1] = p0.y; f[2] = p1.x; f[3] = p1.y;
            f[4] = p2.x; f[5] = p2.y; f[6] = p3.x; f[7] = p3.y;
        }
        #pragma unroll
        for (int j = 0; j < 8; ++j)
            f[j] = fmaxf(fmaf(f[j], s_scale[cb + j], s_shift[cb + j]), 0.f);
        uint4 o;
        *(__half2*)&o.x = __floats2half2_rn(f[0], f[1]);
        *(__half2*)&o.y = __floats2half2_rn(f[2], f[3]);
        *(__half2*)&o.z = __floats2half2_rn(f[4], f[5]);
        *(__half2*)&o.w = __floats2half2_rn(f[6], f[7]);
        ((uint4*)g_y)[i] = o;
    }
}

// ---------------- gather-GEMM conv: BM=128, 8 warps (4m x 2n, m32n32), occ 4 ----------------
__global__ void __launch_bounds__(NT, 4)
k_conv(const void* __restrict__ nbr, int which,
       const float* __restrict__ residual, float* __restrict__ dout)
{
    extern __shared__ char smem[];
    const uint32_t sb = smem_u32(smem);

    const __half* __restrict__ Wh = g_Wh[which];

    const int tid = threadIdx.x;
    const int warp = tid >> 5, lane = tid & 31;
    const int wm = warp >> 1;
    const int wn = warp & 1;
    const int m0 = blockIdx.x * BM;
    const bool is64 = (g_is64 != 0);

    float acc[2][4][4];
    #pragma unroll
    for (int a = 0; a < 2; ++a)
        #pragma unroll
        for (int b = 0; b < 4; ++b)
            #pragma unroll
            for (int c = 0; c < 4; ++c) acc[a][b][c] = 0.f;

    const int r  = tid >> 1;
    const int hs = tid & 1;
    const int gn = (m0 + r < NV) ? (m0 + r) : 0;

    auto fill = [&](int st, int gi, int k) {
        const __half* srcA = g_y + (size_t)gi * CC + hs * 32;
        uint32_t abase = sb + st * STAGE_BYTES;
        #pragma unroll
        for (int j = 0; j < 4; ++j) {
            uint32_t boff = (uint32_t)(r * 128 + (hs * 4 + j) * 16);
            cp16(abase + SW(boff), srcA + j * 8);
        }
        const __half* srcB = Wh + k * 4096;
        uint32_t bbase = abase + A_BYTES;
        cp16(bbase + tid * 16,        srcB + tid * 8);
        cp16(bbase + (tid + NT) * 16, srcB + (tid + NT) * 8);
    };

    {
        int i0 = ld_idx(nbr, is64, gn, 0);
        int i1 = ld_idx(nbr, is64, gn, 1);
        fill(0, i0, 0);
        asm volatile("cp.async.commit_group;\n");
        fill(1, i1, 1);
        asm volatile("cp.async.commit_group;\n");
    }
    int gi_next = ld_idx(nbr, is64, gn, 2);

    for (int k = 0; k < KK; ++k) {
        const int st = k & 1;
        if (k + 1 < KK)
            asm volatile("cp.async.wait_group 1;\n");
        else
            asm volatile("cp.async.wait_group 0;\n");
        __syncthreads();

        const uint32_t abase = sb + st * STAGE_BYTES;
        const uint32_t bbase = abase + A_BYTES;

        #pragma unroll
        for (int ks = 0; ks < 4; ++ks) {
            const int k0 = ks * 16;
            const int arow = wm * 32 + (lane & 15);
            const int acol = k0 + (lane >> 4) * 8;
            const int krow = k0 + ((lane >> 3) & 1) * 8 + (lane & 7);
            const int coll = wn * 32 + (lane >> 4) * 8;

            uint32_t a0[4], a1[4], b0[4], b1[4];
            // issue order: A0, B0, B1, A1 -> first MMA's deps resolve earliest,
            // A1 latency hides under the first 4 MMAs
            {
                uint32_t ad = abase + SW((uint32_t)(arow * 128 + acol * 2));
                asm volatile("ldmatrix.sync.aligned.m8n8.x4.shared.b16 {%0,%1,%2,%3}, [%4];"
                             : "=r"(a0[0]), "=r"(a0[1]), "=r"(a0[2]), "=r"(a0[3]) : "r"(ad));
            }
            {
                uint32_t ad = bbase + SW((uint32_t)(krow * 128 + coll * 2));
                asm volatile("ldmatrix.sync.aligned.m8n8.x4.trans.shared.b16 {%0,%1,%2,%3}, [%4];"
                             : "=r"(b0[0]), "=r"(b0[1]), "=r"(b0[2]), "=r"(b0[3]) : "r"(ad));
                ad = bbase + SW((uint32_t)(krow * 128 + (coll + 16) * 2));
                asm volatile("ldmatrix.sync.aligned.m8n8.x4.trans.shared.b16 {%0,%1,%2,%3}, [%4];"
                             : "=r"(b1[0]), "=r"(b1[1]), "=r"(b1[2]), "=r"(b1[3]) : "r"(ad));
            }
            {
                uint32_t ad = abase + SW((uint32_t)((arow + 16) * 128 + acol * 2));
                asm volatile("ldmatrix.sync.aligned.m8n8.x4.shared.b16 {%0,%1,%2,%3}, [%4];"
                             : "=r"(a1[0]), "=r"(a1[1]), "=r"(a1[2]), "=r"(a1[3]) : "r"(ad));
            }
            #pragma unroll
            for (int mt = 0; mt < 2; ++mt) {
                const uint32_t* A = mt ? a1 : a0;
                #pragma unroll
                for (int nt = 0; nt < 4; ++nt) {
                    const uint32_t* B = (nt < 2) ? b0 : b1;
                    uint32_t bb0 = B[(nt & 1) * 2], bb1 = B[(nt & 1) * 2 + 1];
                    float* C = acc[mt][nt];
                    asm volatile(
                        "mma.sync.aligned.m16n8k16.row.col.f32.f16.f16.f32 "
                        "{%0,%1,%2,%3}, {%4,%5,%6,%7}, {%8,%9}, {%0,%1,%2,%3};"
                        : "+f"(C[0]), "+f"(C[1]), "+f"(C[2]), "+f"(C[3])
                        : "r"(A[0]), "r"(A[1]), "r"(A[2]), "r"(A[3]),
                          "r"(bb0), "r"(bb1));
                }
            }
        }

        if (k + 2 < KK) {
            __syncthreads();
            fill(st, gi_next, k + 2);
            asm volatile("cp.async.commit_group;\n");
            gi_next = ld_idx(nbr, is64, gn, (k + 3 < KK) ? (k + 3) : (KK - 1));
        }
    }

    // ---- epilogue ----
    if (which == 0) {
        float ls[8], lq[8];
        #pragma unroll
        for (int j = 0; j < 8; ++j) { ls[j] = 0.f; lq[j] = 0.f; }

        #pragma unroll
        for (int mt = 0; mt < 2; ++mt) {
            int rbase = m0 + wm * 32 + mt * 16 + (lane >> 2);
            bool v0 = rbase < NV, v1 = rbase + 8 < NV;
            #pragma unroll
            for (int nt = 0; nt < 4; ++nt) {
                int col = wn * 32 + nt * 8 + (lane & 3) * 2;
                float* C = acc[mt][nt];
                if (v0) {
                    size_t o = (size_t)rbase * CC + col;
                    *(__half2*)(g_t16 + o) = __floats2half2_rn(C[0], C[1]);
                    ls[nt * 2]     += C[0]; lq[nt * 2]     += C[0] * C[0];
                    ls[nt * 2 + 1] += C[1]; lq[nt * 2 + 1] += C[1] * C[1];
                }
                if (v1) {
                    size_t o = (size_t)(rbase + 8) * CC + col;
                    *(__half2*)(g_t16 + o) = __floats2half2_rn(C[2], C[3]);
                    ls[nt * 2]     += C[2]; lq[nt * 2]     += C[2] * C[2];
                    ls[nt * 2 + 1] += C[3]; lq[nt * 2 + 1] += C[3] * C[3];
                }
            }
        }
        #pragma unroll
        for (int m = 4; m <= 16; m <<= 1) {
            #pragma unroll
            for (int j = 0; j < 8; ++j) {
                ls[j] += __shfl_xor_sync(0xffffffffu, ls[j], m);
                lq[j] += __shfl_xor_sync(0xffffffffu, lq[j], m);
            }
        }
        float* red = (float*)smem;
        __syncthreads();
        if ((lane >> 2) == 0) {
            #pragma unroll
            for (int j = 0; j < 8; ++j) {
                int cl = (j >> 1) * 8 + (lane & 3) * 2 + (j & 1);
                red[warp * 32 + cl]              = ls[j];
                red[NWARP * 32 + warp * 32 + cl] = lq[j];
            }
        }
        __syncthreads();
        if (tid < 128) {
            int part = tid >> 6, c = tid & 63;
            int cwn = c >> 5, cl = c & 31;
            const float* base = red + part * NWARP * 32;
            float v = 0.f;
            #pragma unroll
            for (int i = 0; i < 4; ++i) v += base[(2 * i + cwn) * 32 + cl];
            atomicAdd(part ? &g_sumsq[1][c] : &g_sum[1][c], v);
        }
    } else {
        // conv2: fp32 out + residual, 8B vector loads/stores
        #pragma unroll
        for (int mt = 0; mt < 2; ++mt) {
            int rbase = m0 + wm * 32 + mt * 16 + (lane >> 2);
            #pragma unroll
            for (int nt = 0; nt < 4; ++nt) {
                int col = wn * 32 + nt * 8 + (lane & 3) * 2;
                float* C = acc[mt][nt];
                if (rbase < NV) {
                    size_t o = (size_t)rbase * CC + col;
                    float2 rv = *(const float2*)(residual + o);
                    float2 v; v.x = C[0] + rv.x; v.y = C[1] + rv.y;
                    *(float2*)(dout + o) = v;
                }
                if (rbase + 8 < NV) {
                    size_t o = (size_t)(rbase + 8) * CC + col;
                    float2 rv = *(const float2*)(residual + o);
                    float2 v; v.x = C[2] + rv.x; v.y = C[3] + rv.y;
                    *(float2*)(dout + o) = v;
                }
            }
        }
    }
}

// ---------------- launch ----------------
extern "C" void kernel_launch(void* const* d_in, const int* in_sizes, int n_in,
                              void* d_out, int out_size) {
    const float* x      = (const float*)d_in[0];
    const void*  nbr    = d_in[1];
    const float* W1     = (const float*)d_in[2];
    const float* gamma1 = (const float*)d_in[3];
    const float* beta1  = (const float*)d_in[4];
    const float* W2     = (const float*)d_in[5];
    const float* gamma2 = (const float*)d_in[6];
    const float* beta2  = (const float*)d_in[7];
    float* out = (float*)d_out;

    const int conv_grid = (NV + BM - 1) / BM;

    static int attr_set = 0;
    if (!attr_set) {
        cudaFuncSetAttribute(k_conv, cudaFuncAttributeMaxDynamicSharedMemorySize,
                             SMEM_TOTAL);
        attr_set = 1;
    }

    k_zero<<<1, 64>>>(nbr);                                         // 1
    k_prep<<<512, 256>>>(x, W1, W2);                                // 2
    k_bnrelu<<<2048, 256>>>(x, gamma1, beta1, 0);                   // 3
    k_conv<<<conv_grid, NT, SMEM_TOTAL>>>(nbr, 0, nullptr, nullptr);// 4 <- ncu
    k_bnrelu<<<2048, 256>>>(nullptr, gamma2, beta2, 1);             // 5
    k_conv<<<conv_grid, NT, SMEM_TOTAL>>>(nbr, 1, x, out);          // 6
}